// round 2
// baseline (speedup 1.0000x reference)
#include <cuda_runtime.h>

// GuidedFilter: causal box window of width R=20 (trailing, clamped prefix at edges),
// separable H then W.  Stage1: box{I,p,Ip,I2} -> A,b.  Stage2: box{A,b} -> q.
// Edge pixels (i<R or j<R) replicate the reference's fp32 rounding exactly:
// sequential cumsum order, no FMA contraction, true division by N.

#define Bn 8
#define Cn 3
#define Hn 1024
#define Wn 1024
#define NIMG (Bn * Cn)
#define R 20
#define SW 256                 // output columns per CTA strip
#define NSTRIP (Wn / SW)       // 4
#define TPB 288                // 9 warps: warp0 = 32-col left halo, warps1..8 = 256 outputs
#define NBAND 3
#define BANDH 342

// Scratch for (A,b) interleaved per pixel. __device__ global => no runtime alloc.
__device__ float2 g_AB[(size_t)NIMG * Hn * Wn];

__device__ __forceinline__ float warp_incl_scan(float v, int lane) {
#pragma unroll
    for (int d = 1; d < 32; d <<= 1) {
        float n = __shfl_up_sync(0xffffffffu, v, d);
        if (lane >= d) v += n;
    }
    return v;
}

// Window sum of width 20 ending at this lane, from warp inclusive prefix P and the
// previous warp's prefixes stored at buf[(wid-1)*20 + (srcLane-12)]. wid >= 1 only.
__device__ __forceinline__ float window20(float P, int lane, int wid, const float* buf) {
    float up = __shfl_up_sync(0xffffffffu, P, 20);
    if (lane >= 20) {
        return P - up;
    } else {
        const float* pb = buf + (wid - 1) * 20;
        return P + (pb[19] - pb[lane]);
    }
}

// Sequential-order inclusive prefix over lanes 0..19 (value valid for lane < 20).
__device__ __forceinline__ float seq_prefix20(float v, int lane) {
    float s = 0.0f;
#pragma unroll
    for (int k = 0; k < R; ++k) {
        float x = __shfl_sync(0xffffffffu, v, k);
        if (lane >= k) s = __fadd_rn(s, x);
    }
    return s;
}

__global__ void __launch_bounds__(TPB, 2)
gf_stage1(const float* __restrict__ gI, const float* __restrict__ gP)
{
    __shared__ float sbuf[2][4][9 * 20];

    const int t    = threadIdx.x;
    const int lane = t & 31;
    const int wid  = t >> 5;
    const int strip = blockIdx.x, band = blockIdx.y, img = blockIdx.z;

    const int c0 = strip * SW;
    const int jg = c0 - 32 + t;
    const bool incol = (jg >= 0);
    const int r0 = band * BANDH;
    const int r1 = (band == NBAND - 1) ? Hn : (r0 + BANDH);
    const int gstart = (r0 - (R - 1) > 0) ? (r0 - (R - 1)) : 0;
    const int rowsTotal = r1 - gstart;

    const float* Ib = gI + (size_t)img * Hn * Wn;
    const float* Pb = gP + (size_t)img * Hn * Wn;
    float2* ABb = g_AB + (size_t)img * Hn * Wn;

    const bool isOut = (t >= 32);
    const int jout = c0 + (t - 32);
    const int nj = (jout + 1 < R) ? (jout + 1) : R;
    const float Ncf = (float)nj;
    const bool edgeWarp = (strip == 0) && (wid == 1);   // owns cols 0..31
    const float inv400 = 1.0f / 400.0f;

    float rI[R], rP[R];
#pragma unroll
    for (int k = 0; k < R; ++k) { rI[k] = 0.0f; rP[k] = 0.0f; }
    float vI = 0.0f, vP = 0.0f, vIP = 0.0f, vII = 0.0f;

    for (int base = 0; base < rowsTotal; base += R) {
#pragma unroll
        for (int k = 0; k < R; ++k) {
            const int rr = base + k;
            if (rr < rowsTotal) {
                const int gi = gstart + rr;
                float iv = 0.0f, pv = 0.0f;
                if (incol) {
                    const size_t off = (size_t)gi * Wn + jg;
                    iv = __ldg(Ib + off);
                    pv = __ldg(Pb + off);
                }
                const float io = rI[k], po = rP[k];
                const float ipn = __fmul_rn(iv, pv);
                const float iin = __fmul_rn(iv, iv);
                const float ipo = __fmul_rn(io, po);
                const float iio = __fmul_rn(io, io);
                // Sequential cumsum order for edge rows (old = 0 exactly there).
                vI  = __fsub_rn(__fadd_rn(vI,  iv),  io);
                vP  = __fsub_rn(__fadd_rn(vP,  pv),  po);
                vIP = __fsub_rn(__fadd_rn(vIP, ipn), ipo);
                vII = __fsub_rn(__fadd_rn(vII, iin), iio);
                rI[k] = iv; rP[k] = pv;

                if (gi >= r0) {
                    const int sel = rr & 1;
                    float P0 = warp_incl_scan(vI,  lane);
                    float P1 = warp_incl_scan(vP,  lane);
                    float P2 = warp_incl_scan(vIP, lane);
                    float P3 = warp_incl_scan(vII, lane);
                    if (lane >= 12) {
                        const int bi = wid * 20 + (lane - 12);
                        sbuf[sel][0][bi] = P0;
                        sbuf[sel][1][bi] = P1;
                        sbuf[sel][2][bi] = P2;
                        sbuf[sel][3][bi] = P3;
                    }
                    __syncthreads();
                    if (isOut) {
                        float h0 = window20(P0, lane, wid, sbuf[sel][0]);
                        float h1 = window20(P1, lane, wid, sbuf[sel][1]);
                        float h2 = window20(P2, lane, wid, sbuf[sel][2]);
                        float h3 = window20(P3, lane, wid, sbuf[sel][3]);
                        if (edgeWarp) {
                            // cols 0..19: exact sequential-order prefix (matches ref cumsum)
                            float s0 = seq_prefix20(vI,  lane);
                            float s1 = seq_prefix20(vP,  lane);
                            float s2 = seq_prefix20(vIP, lane);
                            float s3 = seq_prefix20(vII, lane);
                            if (lane < R) { h0 = s0; h1 = s1; h2 = s2; h3 = s3; }
                        }
                        float mI, mP, mIp, mII;
                        if ((gi < R) || edgeWarp) {
                            const float Nrf = (gi + 1 < R) ? (float)(gi + 1) : (float)R;
                            const float Nf = __fmul_rn(Nrf, Ncf);  // exact small int
                            mI  = __fdiv_rn(h0, Nf);
                            mP  = __fdiv_rn(h1, Nf);
                            mIp = __fdiv_rn(h2, Nf);
                            mII = __fdiv_rn(h3, Nf);
                        } else {
                            mI  = h0 * inv400;
                            mP  = h1 * inv400;
                            mIp = h2 * inv400;
                            mII = h3 * inv400;
                        }
                        const float cov = __fsub_rn(mIp, __fmul_rn(mI, mP));
                        const float var = __fsub_rn(mII, __fmul_rn(mI, mI));
                        const float A = __fdiv_rn(cov, __fadd_rn(var, 1e-8f));
                        const float b = __fsub_rn(mP, __fmul_rn(A, mI));
                        ABb[(size_t)gi * Wn + jout] = make_float2(A, b);
                    }
                }
            }
        }
        // Exact refresh of vertical running sums (sequential ring order => for the
        // first chunk this is bit-identical to the running value; later it kills drift).
        if (base + R <= rowsTotal) {
            float aI = 0.0f, aP = 0.0f, aIP = 0.0f, aII = 0.0f;
#pragma unroll
            for (int k = 0; k < R; ++k) {
                aI  = __fadd_rn(aI,  rI[k]);
                aP  = __fadd_rn(aP,  rP[k]);
                aIP = __fadd_rn(aIP, __fmul_rn(rI[k], rP[k]));
                aII = __fadd_rn(aII, __fmul_rn(rI[k], rI[k]));
            }
            vI = aI; vP = aP; vIP = aIP; vII = aII;
        }
    }
}

__global__ void __launch_bounds__(TPB, 2)
gf_stage2(const float* __restrict__ gI, float* __restrict__ gQ)
{
    __shared__ float sbuf[2][2][9 * 20];

    const int t    = threadIdx.x;
    const int lane = t & 31;
    const int wid  = t >> 5;
    const int strip = blockIdx.x, band = blockIdx.y, img = blockIdx.z;

    const int c0 = strip * SW;
    const int jg = c0 - 32 + t;
    const bool incol = (jg >= 0);
    const int r0 = band * BANDH;
    const int r1 = (band == NBAND - 1) ? Hn : (r0 + BANDH);
    const int gstart = (r0 - (R - 1) > 0) ? (r0 - (R - 1)) : 0;
    const int rowsTotal = r1 - gstart;

    const float* Ib = gI + (size_t)img * Hn * Wn;
    const float2* ABb = g_AB + (size_t)img * Hn * Wn;
    float* Qb = gQ + (size_t)img * Hn * Wn;

    const bool isOut = (t >= 32);
    const int jout = c0 + (t - 32);
    const int nj = (jout + 1 < R) ? (jout + 1) : R;
    const float Ncf = (float)nj;
    const bool edgeWarp = (strip == 0) && (wid == 1);
    const float inv400 = 1.0f / 400.0f;

    float rA[R], rB[R];
#pragma unroll
    for (int k = 0; k < R; ++k) { rA[k] = 0.0f; rB[k] = 0.0f; }
    float vA = 0.0f, vB = 0.0f;

    for (int base = 0; base < rowsTotal; base += R) {
#pragma unroll
        for (int k = 0; k < R; ++k) {
            const int rr = base + k;
            if (rr < rowsTotal) {
                const int gi = gstart + rr;
                float av = 0.0f, bv = 0.0f;
                if (incol) {
                    const float2 ab = __ldg(ABb + (size_t)gi * Wn + jg);
                    av = ab.x; bv = ab.y;
                }
                vA = __fsub_rn(__fadd_rn(vA, av), rA[k]);
                vB = __fsub_rn(__fadd_rn(vB, bv), rB[k]);
                rA[k] = av; rB[k] = bv;

                if (gi >= r0) {
                    const int sel = rr & 1;
                    float P0 = warp_incl_scan(vA, lane);
                    float P1 = warp_incl_scan(vB, lane);
                    if (lane >= 12) {
                        const int bi = wid * 20 + (lane - 12);
                        sbuf[sel][0][bi] = P0;
                        sbuf[sel][1][bi] = P1;
                    }
                    __syncthreads();
                    if (isOut) {
                        float hA = window20(P0, lane, wid, sbuf[sel][0]);
                        float hB = window20(P1, lane, wid, sbuf[sel][1]);
                        if (edgeWarp) {
                            float s0 = seq_prefix20(vA, lane);
                            float s1 = seq_prefix20(vB, lane);
                            if (lane < R) { hA = s0; hB = s1; }
                        }
                        float mA, mB;
                        if ((gi < R) || edgeWarp) {
                            const float Nrf = (gi + 1 < R) ? (float)(gi + 1) : (float)R;
                            const float Nf = __fmul_rn(Nrf, Ncf);
                            mA = __fdiv_rn(hA, Nf);
                            mB = __fdiv_rn(hB, Nf);
                        } else {
                            mA = hA * inv400;
                            mB = hB * inv400;
                        }
                        const float Iv = __ldg(Ib + (size_t)gi * Wn + jout);
                        Qb[(size_t)gi * Wn + jout] = __fadd_rn(__fmul_rn(mA, Iv), mB);
                    }
                }
            }
        }
        if (base + R <= rowsTotal) {
            float aA = 0.0f, aB = 0.0f;
#pragma unroll
            for (int k = 0; k < R; ++k) {
                aA = __fadd_rn(aA, rA[k]);
                aB = __fadd_rn(aB, rB[k]);
            }
            vA = aA; vB = aB;
        }
    }
}

extern "C" void kernel_launch(void* const* d_in, const int* in_sizes, int n_in,
                              void* d_out, int out_size)
{
    (void)in_sizes; (void)n_in; (void)out_size;
    const float* I = (const float*)d_in[0];
    const float* p = (const float*)d_in[1];
    float* q = (float*)d_out;

    dim3 grid(NSTRIP, NBAND, NIMG);
    gf_stage1<<<grid, TPB>>>(I, p);
    gf_stage2<<<grid, TPB>>>(I, q);
}

// round 4
// speedup vs baseline: 2.4922x; 2.4922x over previous
#include <cuda_runtime.h>

// GuidedFilter, causal box window R=20 (trailing, clamped prefix at edges), H then W.
// Stage1: box{I,p,Ip,I2} -> A,b (scratch).  Stage2: box{A,b} -> q.
//
// Layout: 1 warp = 128 columns (4 per lane, float4). Vertical box via running
// add/subtract re-reading row gi-20 from global (L2-hot) -- subtraction gated on
// gi >= gstart+R so band warm-up never subtracts rows that were not accumulated.
// Horizontal box: in-thread prefix + 32-lane shfl scan; window-20 == 5-lane
// shfl_up (20 = 5*4). Strip halo (20 cols) maintained redundantly by lanes 0-4
// with a 5-lane mini-scan. No __syncthreads, no smem, warps independent.
// Edge exactness (matches reference fp32 rounding where var~0): no-FMA epilogue,
// true division by exact N at edges, sequential in-thread prefixes.

#define Hn 1024
#define Wn 1024
#define NIMG 24
#define R 20
#define NBAND 16
#define BANDH 64
#define TPB 128

// Scratch: (A,b) interleaved, 2 pixels per float4. __device__ global => no alloc.
__device__ float4 g_AB4[(size_t)NIMG * Hn * (Wn / 2)];

// Horizontal window of width 20 for 4 elements/lane.
__device__ __forceinline__ void hwindow(const float v[4], const float hv[4],
                                        bool hasHalo, int lane, float w[4])
{
    // in-thread sequential inclusive prefixes
    const float p0 = v[0];
    const float p1 = __fadd_rn(p0, v[1]);
    const float p2 = __fadd_rn(p1, v[2]);
    const float p3 = __fadd_rn(p2, v[3]);
    const float total = p3;

    // 32-lane inclusive scan of thread totals
    float S = total;
#pragma unroll
    for (int d = 1; d < 32; d <<= 1) {
        float n = __shfl_up_sync(0xffffffffu, S, d);
        if (lane >= d) S = __fadd_rn(S, n);
    }
    float base = __fsub_rn(S, total);      // exclusive prefix

    if (!hasHalo) {
        // strip 0: sequential-order cross-lane base for cols 0..19 (lanes 0..4)
        float sb = 0.0f;
#pragma unroll
        for (int k = 0; k < 4; ++k) {
            float tk = __shfl_sync(0xffffffffu, total, k);
            if (lane > k) sb = __fadd_rn(sb, tk);
        }
        if (lane < 5) base = sb;
    }

    const float P0 = __fadd_rn(base, p0);
    const float P1 = __fadd_rn(base, p1);
    const float P2 = __fadd_rn(base, p2);
    const float P3 = __fadd_rn(base, p3);

    // subtrahend: inclusive prefix 20 columns back == 5 lanes up
    float s0 = __shfl_up_sync(0xffffffffu, P0, 5);
    float s1 = __shfl_up_sync(0xffffffffu, P1, 5);
    float s2 = __shfl_up_sync(0xffffffffu, P2, 5);
    float s3 = __shfl_up_sync(0xffffffffu, P3, 5);

    if (hasHalo) {
        // halo inclusive prefixes over 20 elems held by lanes 0..4
        const float hp0 = hv[0];
        const float hp1 = __fadd_rn(hp0, hv[1]);
        const float hp2 = __fadd_rn(hp1, hv[2]);
        const float hp3 = __fadd_rn(hp2, hv[3]);
        float hS = hp3;
#pragma unroll
        for (int d = 1; d < 8; d <<= 1) {
            float n = __shfl_up_sync(0xffffffffu, hS, d);
            if (lane >= d) hS = __fadd_rn(hS, n);
        }
        const float Hs = __shfl_sync(0xffffffffu, hS, 4);   // total halo sum
        const float hbase = __fsub_rn(hS, hp3);
        if (lane < 5) {
            s0 = __fsub_rn(__fadd_rn(hbase, hp0), Hs);
            s1 = __fsub_rn(__fadd_rn(hbase, hp1), Hs);
            s2 = __fsub_rn(__fadd_rn(hbase, hp2), Hs);
            s3 = __fsub_rn(__fadd_rn(hbase, hp3), Hs);
        }
    } else {
        if (lane < 5) { s0 = 0.0f; s1 = 0.0f; s2 = 0.0f; s3 = 0.0f; }
    }

    w[0] = __fsub_rn(P0, s0);
    w[1] = __fsub_rn(P1, s1);
    w[2] = __fsub_rn(P2, s2);
    w[3] = __fsub_rn(P3, s3);
}

__global__ void __launch_bounds__(TPB, 4)
gf_stage1(const float* __restrict__ gI, const float* __restrict__ gP)
{
    const int lane = threadIdx.x & 31;
    const int wid  = threadIdx.x >> 5;
    const int img  = blockIdx.z;
    const int c0   = (blockIdx.x * 4 + wid) * 128;
    const bool hasHalo = (c0 != 0);
    const int r0 = blockIdx.y * BANDH;
    const int r1 = r0 + BANDH;
    const int gstart = (r0 >= R - 1) ? (r0 - (R - 1)) : 0;
    const int subStart = gstart + R;       // first row whose gi-R was actually added

    const float4* I4  = (const float4*)(gI + (size_t)img * Hn * Wn);
    const float4* P4  = (const float4*)(gP + (size_t)img * Hn * Wn);
    float4* AB4 = g_AB4 + (size_t)img * Hn * (Wn / 2);

    const int mi = (c0 >> 2) + lane;               // float4 index within row (main)
    const int hi = ((c0 - 20) >> 2) + lane;        // float4 index within row (halo, lanes<5)

    float vI[4]  = {0,0,0,0}, vP[4]  = {0,0,0,0};
    float vIP[4] = {0,0,0,0}, vII[4] = {0,0,0,0};
    float hI[4]  = {0,0,0,0}, hP[4]  = {0,0,0,0};
    float hIP[4] = {0,0,0,0}, hII[4] = {0,0,0,0};
    const float inv400 = 1.0f / 400.0f;

    for (int gi = gstart; gi < r1; ++gi) {
        const int rbase = gi << 8;                 // gi * 256 float4/row
        const float4 In = I4[rbase + mi];
        const float4 Pn = P4[rbase + mi];
        float4 Io = make_float4(0.f,0.f,0.f,0.f), Po = Io;
        float4 HIn = Io, HPn = Io, HIo = Io, HPo = Io;
        const bool doSub = (gi >= subStart);
        const int obase = (gi - R) << 8;
        if (doSub) { Io = I4[obase + mi]; Po = P4[obase + mi]; }
        if (hasHalo && lane < 5) {
            HIn = I4[rbase + hi]; HPn = P4[rbase + hi];
            if (doSub) { HIo = I4[obase + hi]; HPo = P4[obase + hi]; }
        }

        {
            const float in_[4] = {In.x, In.y, In.z, In.w};
            const float pn_[4] = {Pn.x, Pn.y, Pn.z, Pn.w};
            const float io_[4] = {Io.x, Io.y, Io.z, Io.w};
            const float po_[4] = {Po.x, Po.y, Po.z, Po.w};
#pragma unroll
            for (int e = 0; e < 4; ++e) {
                vI[e]  = __fsub_rn(__fadd_rn(vI[e],  in_[e]), io_[e]);
                vP[e]  = __fsub_rn(__fadd_rn(vP[e],  pn_[e]), po_[e]);
                vIP[e] = __fsub_rn(__fadd_rn(vIP[e], __fmul_rn(in_[e], pn_[e])),
                                   __fmul_rn(io_[e], po_[e]));
                vII[e] = __fsub_rn(__fadd_rn(vII[e], __fmul_rn(in_[e], in_[e])),
                                   __fmul_rn(io_[e], io_[e]));
            }
        }
        if (hasHalo) {
            const float in_[4] = {HIn.x, HIn.y, HIn.z, HIn.w};
            const float pn_[4] = {HPn.x, HPn.y, HPn.z, HPn.w};
            const float io_[4] = {HIo.x, HIo.y, HIo.z, HIo.w};
            const float po_[4] = {HPo.x, HPo.y, HPo.z, HPo.w};
#pragma unroll
            for (int e = 0; e < 4; ++e) {
                hI[e]  = __fsub_rn(__fadd_rn(hI[e],  in_[e]), io_[e]);
                hP[e]  = __fsub_rn(__fadd_rn(hP[e],  pn_[e]), po_[e]);
                hIP[e] = __fsub_rn(__fadd_rn(hIP[e], __fmul_rn(in_[e], pn_[e])),
                                   __fmul_rn(io_[e], po_[e]));
                hII[e] = __fsub_rn(__fadd_rn(hII[e], __fmul_rn(in_[e], in_[e])),
                                   __fmul_rn(io_[e], io_[e]));
            }
        }

        if (gi >= r0) {
            float w0[4], w1[4], w2[4], w3[4];
            hwindow(vI,  hI,  hasHalo, lane, w0);
            hwindow(vP,  hP,  hasHalo, lane, w1);
            hwindow(vIP, hIP, hasHalo, lane, w2);
            hwindow(vII, hII, hasHalo, lane, w3);

            const bool divpath = (gi + 1 < R) || (!hasHalo && lane < 5);
            const float Nrf = (gi + 1 < R) ? (float)(gi + 1) : 20.0f;
            float A_[4], b_[4];
#pragma unroll
            for (int e = 0; e < 4; ++e) {
                float m0, m1, m2, m3;
                if (divpath) {
                    const int colp1 = c0 + lane * 4 + e + 1;
                    const float Ncf = (colp1 < R) ? (float)colp1 : 20.0f;
                    const float Nf = __fmul_rn(Nrf, Ncf);   // exact small integer
                    m0 = __fdiv_rn(w0[e], Nf); m1 = __fdiv_rn(w1[e], Nf);
                    m2 = __fdiv_rn(w2[e], Nf); m3 = __fdiv_rn(w3[e], Nf);
                } else {
                    m0 = __fmul_rn(w0[e], inv400); m1 = __fmul_rn(w1[e], inv400);
                    m2 = __fmul_rn(w2[e], inv400); m3 = __fmul_rn(w3[e], inv400);
                }
                const float cov = __fsub_rn(m2, __fmul_rn(m0, m1));
                const float var = __fsub_rn(m3, __fmul_rn(m0, m0));
                A_[e] = __fdiv_rn(cov, __fadd_rn(var, 1e-8f));
                b_[e] = __fsub_rn(m1, __fmul_rn(A_[e], m0));
            }
            const int sbase = gi * (Wn / 2) + (c0 >> 1) + lane * 2;
            AB4[sbase]     = make_float4(A_[0], b_[0], A_[1], b_[1]);
            AB4[sbase + 1] = make_float4(A_[2], b_[2], A_[3], b_[3]);
        }
    }
}

__global__ void __launch_bounds__(TPB, 4)
gf_stage2(const float* __restrict__ gI, float* __restrict__ gQ)
{
    const int lane = threadIdx.x & 31;
    const int wid  = threadIdx.x >> 5;
    const int img  = blockIdx.z;
    const int c0   = (blockIdx.x * 4 + wid) * 128;
    const bool hasHalo = (c0 != 0);
    const int r0 = blockIdx.y * BANDH;
    const int r1 = r0 + BANDH;
    const int gstart = (r0 >= R - 1) ? (r0 - (R - 1)) : 0;
    const int subStart = gstart + R;

    const float4* I4  = (const float4*)(gI + (size_t)img * Hn * Wn);
    const float4* AB4 = g_AB4 + (size_t)img * Hn * (Wn / 2);
    float4* Q4 = (float4*)(gQ + (size_t)img * Hn * Wn);

    const int mi = (c0 >> 2) + lane;
    const int ai = (c0 >> 1) + lane * 2;           // float4 index into AB row (main)
    const int hai = ((c0 - 20) >> 1) + lane * 2;   // halo (lanes<5)

    float vA[4] = {0,0,0,0}, vB[4] = {0,0,0,0};
    float hA[4] = {0,0,0,0}, hB[4] = {0,0,0,0};
    const float inv400 = 1.0f / 400.0f;

    for (int gi = gstart; gi < r1; ++gi) {
        const int abase = gi * (Wn / 2);
        const float4 u0 = AB4[abase + ai];
        const float4 u1 = AB4[abase + ai + 1];
        float4 o0 = make_float4(0.f,0.f,0.f,0.f), o1 = o0;
        float4 hu0 = o0, hu1 = o0, ho0 = o0, ho1 = o0;
        const bool doSub = (gi >= subStart);
        const int obase = (gi - R) * (Wn / 2);
        if (doSub) { o0 = AB4[obase + ai]; o1 = AB4[obase + ai + 1]; }
        if (hasHalo && lane < 5) {
            hu0 = AB4[abase + hai]; hu1 = AB4[abase + hai + 1];
            if (doSub) { ho0 = AB4[obase + hai]; ho1 = AB4[obase + hai + 1]; }
        }

        {
            const float an[4] = {u0.x, u0.z, u1.x, u1.z};
            const float bn[4] = {u0.y, u0.w, u1.y, u1.w};
            const float ao[4] = {o0.x, o0.z, o1.x, o1.z};
            const float bo[4] = {o0.y, o0.w, o1.y, o1.w};
#pragma unroll
            for (int e = 0; e < 4; ++e) {
                vA[e] = __fsub_rn(__fadd_rn(vA[e], an[e]), ao[e]);
                vB[e] = __fsub_rn(__fadd_rn(vB[e], bn[e]), bo[e]);
            }
        }
        if (hasHalo) {
            const float an[4] = {hu0.x, hu0.z, hu1.x, hu1.z};
            const float bn[4] = {hu0.y, hu0.w, hu1.y, hu1.w};
            const float ao[4] = {ho0.x, ho0.z, ho1.x, ho1.z};
            const float bo[4] = {ho0.y, ho0.w, ho1.y, ho1.w};
#pragma unroll
            for (int e = 0; e < 4; ++e) {
                hA[e] = __fsub_rn(__fadd_rn(hA[e], an[e]), ao[e]);
                hB[e] = __fsub_rn(__fadd_rn(hB[e], bn[e]), bo[e]);
            }
        }

        if (gi >= r0) {
            float wA[4], wB[4];
            hwindow(vA, hA, hasHalo, lane, wA);
            hwindow(vB, hB, hasHalo, lane, wB);

            const bool divpath = (gi + 1 < R) || (!hasHalo && lane < 5);
            const float Nrf = (gi + 1 < R) ? (float)(gi + 1) : 20.0f;
            const float4 Iv = I4[(gi << 8) + mi];
            const float iv_[4] = {Iv.x, Iv.y, Iv.z, Iv.w};
            float q_[4];
#pragma unroll
            for (int e = 0; e < 4; ++e) {
                float mA, mB;
                if (divpath) {
                    const int colp1 = c0 + lane * 4 + e + 1;
                    const float Ncf = (colp1 < R) ? (float)colp1 : 20.0f;
                    const float Nf = __fmul_rn(Nrf, Ncf);
                    mA = __fdiv_rn(wA[e], Nf);
                    mB = __fdiv_rn(wB[e], Nf);
                } else {
                    mA = __fmul_rn(wA[e], inv400);
                    mB = __fmul_rn(wB[e], inv400);
                }
                q_[e] = __fadd_rn(__fmul_rn(mA, iv_[e]), mB);
            }
            Q4[(gi << 8) + mi] = make_float4(q_[0], q_[1], q_[2], q_[3]);
        }
    }
}

extern "C" void kernel_launch(void* const* d_in, const int* in_sizes, int n_in,
                              void* d_out, int out_size)
{
    (void)in_sizes; (void)n_in; (void)out_size;
    const float* I = (const float*)d_in[0];
    const float* p = (const float*)d_in[1];
    float* q = (float*)d_out;

    dim3 grid(2, NBAND, NIMG);   // 2 CTAs x-wise (4 warps * 128 cols each), 16 bands, 24 images
    gf_stage1<<<grid, TPB>>>(I, p);
    gf_stage2<<<grid, TPB>>>(I, q);
}

// round 5
// speedup vs baseline: 2.8275x; 1.1346x over previous
#include <cuda_runtime.h>

// GuidedFilter, causal box window R=20 (trailing, clamped prefix at edges), H then W.
// Stage1: box{I,p,Ip,I2} -> A,b (scratch).  Stage2: box{A,b} -> q.
//
// 1 warp = 128 columns (4/lane, float4). Vertical box: running add/subtract,
// re-reading row gi-20 from global (L2-hot), subtraction gated on band warm-up.
// Horizontal box of width 20 == 5-lane reach: w_e(l) = p_e(l) + sum_{k=1..5} T(l-k)
// - p_e(l-5), built from INDEPENDENT shfls (no dependent scan chains).
// 20-col strip halo held redundantly by lanes 0..4; halo suffix via independent
// shfl_down. No smem, no __syncthreads.
// Edge exactness (var~0 pixels match reference fp32 rounding): sequential
// in-thread prefixes, sequential vertical adds, exact division by integer N at
// edges, no FMA contraction in the epilogue. Interior uses __fdividef (var~1/12).

#define Hn 1024
#define Wn 1024
#define NIMG 24
#define R 20
#define NBAND 16
#define BANDH 64
#define TPB 128

__device__ float4 g_AB4[(size_t)NIMG * Hn * (Wn / 2)];

// Horizontal window of width 20 for 4 elements/lane; all shfls independent.
__device__ __forceinline__ void hwindow(const float v[4], const float hv[4],
                                        bool hasHalo, int lane, float w[4])
{
    // in-thread sequential inclusive prefixes (exactness-critical at lane 0)
    const float p0 = v[0];
    const float p1 = __fadd_rn(p0, v[1]);
    const float p2 = __fadd_rn(p1, v[2]);
    const float p3 = __fadd_rn(p2, v[3]);
    const float T  = p3;

    // independent shfls (single latency, pipelined)
    const float t1 = __shfl_up_sync(0xffffffffu, T, 1);
    const float t2 = __shfl_up_sync(0xffffffffu, T, 2);
    const float t3 = __shfl_up_sync(0xffffffffu, T, 3);
    const float t4 = __shfl_up_sync(0xffffffffu, T, 4);
    const float t5 = __shfl_up_sync(0xffffffffu, T, 5);
    const float s0 = __shfl_up_sync(0xffffffffu, p0, 5);
    const float s1 = __shfl_up_sync(0xffffffffu, p1, 5);
    const float s2 = __shfl_up_sync(0xffffffffu, p2, 5);
    const float s3 = __shfl_up_sync(0xffffffffu, p3, 5);

    float sumT = 0.0f;
    if (lane >= 1) sumT = __fadd_rn(sumT, t1);
    if (lane >= 2) sumT = __fadd_rn(sumT, t2);
    if (lane >= 3) sumT = __fadd_rn(sumT, t3);
    if (lane >= 4) sumT = __fadd_rn(sumT, t4);
    if (lane >= 5) sumT = __fadd_rn(sumT, t5);

    // halo prefixes (lanes 0..4 hold the 20 halo cols); garbage elsewhere, unused
    const float hp0 = hv[0];
    const float hp1 = __fadd_rn(hp0, hv[1]);
    const float hp2 = __fadd_rn(hp1, hv[2]);
    const float hp3 = __fadd_rn(hp2, hv[3]);
    const float d1 = __shfl_down_sync(0xffffffffu, hp3, 1);
    const float d2 = __shfl_down_sync(0xffffffffu, hp3, 2);
    const float d3 = __shfl_down_sync(0xffffffffu, hp3, 3);
    const float d4 = __shfl_down_sync(0xffffffffu, hp3, 4);
    float hs = 0.0f;                       // suffix of halo lane-totals after this lane
    if (lane <= 3) hs = __fadd_rn(hs, d1);
    if (lane <= 2) hs = __fadd_rn(hs, d2);
    if (lane <= 1) hs = __fadd_rn(hs, d3);
    if (lane == 0) hs = __fadd_rn(hs, d4);

    const float hq0 = __fsub_rn(hp3, hp0);
    const float hq1 = __fsub_rn(hp3, hp1);
    const float hq2 = __fsub_rn(hp3, hp2);

    const float c0_ = __fadd_rn(p0, sumT);
    const float c1_ = __fadd_rn(p1, sumT);
    const float c2_ = __fadd_rn(p2, sumT);
    const float c3_ = __fadd_rn(p3, sumT);

    if (lane >= 5) {
        w[0] = __fsub_rn(c0_, s0);
        w[1] = __fsub_rn(c1_, s1);
        w[2] = __fsub_rn(c2_, s2);
        w[3] = __fsub_rn(c3_, s3);
    } else if (hasHalo) {
        w[0] = __fadd_rn(__fadd_rn(c0_, hs), hq0);
        w[1] = __fadd_rn(__fadd_rn(c1_, hs), hq1);
        w[2] = __fadd_rn(__fadd_rn(c2_, hs), hq2);
        w[3] = __fadd_rn(c3_, hs);
    } else {                               // strip 0: clamped prefix
        w[0] = c0_;
        w[1] = c1_;
        w[2] = c2_;
        w[3] = c3_;
    }
}

__global__ void __launch_bounds__(TPB, 4)
gf_stage1(const float* __restrict__ gI, const float* __restrict__ gP)
{
    const int lane = threadIdx.x & 31;
    const int wid  = threadIdx.x >> 5;
    const int img  = blockIdx.z;
    const int c0   = (blockIdx.x * 4 + wid) * 128;
    const bool hasHalo = (c0 != 0);
    const int r0 = blockIdx.y * BANDH;
    const int r1 = r0 + BANDH;
    const int gstart = (r0 >= R - 1) ? (r0 - (R - 1)) : 0;
    const int subStart = gstart + R;

    const float4* I4  = (const float4*)(gI + (size_t)img * Hn * Wn);
    const float4* P4  = (const float4*)(gP + (size_t)img * Hn * Wn);
    float4* AB4 = g_AB4 + (size_t)img * Hn * (Wn / 2);

    const int mi = (c0 >> 2) + lane;
    const int hi = ((c0 - 20) >> 2) + lane;

    float vI[4]  = {0,0,0,0}, vP[4]  = {0,0,0,0};
    float vIP[4] = {0,0,0,0}, vII[4] = {0,0,0,0};
    float hI[4]  = {0,0,0,0}, hP[4]  = {0,0,0,0};
    float hIP[4] = {0,0,0,0}, hII[4] = {0,0,0,0};
    const float inv400 = 1.0f / 400.0f;

    for (int gi = gstart; gi < r1; ++gi) {
        const int rbase = gi << 8;
        const float4 In = I4[rbase + mi];
        const float4 Pn = P4[rbase + mi];
        float4 Io = make_float4(0.f,0.f,0.f,0.f), Po = Io;
        float4 HIn = Io, HPn = Io, HIo = Io, HPo = Io;
        const bool doSub = (gi >= subStart);
        const int obase = (gi - R) << 8;
        if (doSub) { Io = I4[obase + mi]; Po = P4[obase + mi]; }
        if (hasHalo && lane < 5) {
            HIn = I4[rbase + hi]; HPn = P4[rbase + hi];
            if (doSub) { HIo = I4[obase + hi]; HPo = P4[obase + hi]; }
        }

        {
            const float in_[4] = {In.x, In.y, In.z, In.w};
            const float pn_[4] = {Pn.x, Pn.y, Pn.z, Pn.w};
            const float io_[4] = {Io.x, Io.y, Io.z, Io.w};
            const float po_[4] = {Po.x, Po.y, Po.z, Po.w};
#pragma unroll
            for (int e = 0; e < 4; ++e) {
                vI[e]  = __fsub_rn(__fadd_rn(vI[e],  in_[e]), io_[e]);
                vP[e]  = __fsub_rn(__fadd_rn(vP[e],  pn_[e]), po_[e]);
                vIP[e] = __fsub_rn(__fadd_rn(vIP[e], __fmul_rn(in_[e], pn_[e])),
                                   __fmul_rn(io_[e], po_[e]));
                vII[e] = __fsub_rn(__fadd_rn(vII[e], __fmul_rn(in_[e], in_[e])),
                                   __fmul_rn(io_[e], io_[e]));
            }
        }
        if (hasHalo) {
            const float in_[4] = {HIn.x, HIn.y, HIn.z, HIn.w};
            const float pn_[4] = {HPn.x, HPn.y, HPn.z, HPn.w};
            const float io_[4] = {HIo.x, HIo.y, HIo.z, HIo.w};
            const float po_[4] = {HPo.x, HPo.y, HPo.z, HPo.w};
#pragma unroll
            for (int e = 0; e < 4; ++e) {
                hI[e]  = __fsub_rn(__fadd_rn(hI[e],  in_[e]), io_[e]);
                hP[e]  = __fsub_rn(__fadd_rn(hP[e],  pn_[e]), po_[e]);
                hIP[e] = __fsub_rn(__fadd_rn(hIP[e], __fmul_rn(in_[e], pn_[e])),
                                   __fmul_rn(io_[e], po_[e]));
                hII[e] = __fsub_rn(__fadd_rn(hII[e], __fmul_rn(in_[e], in_[e])),
                                   __fmul_rn(io_[e], io_[e]));
            }
        }

        if (gi >= r0) {
            float w0[4], w1[4], w2[4], w3[4];
            hwindow(vI,  hI,  hasHalo, lane, w0);
            hwindow(vP,  hP,  hasHalo, lane, w1);
            hwindow(vIP, hIP, hasHalo, lane, w2);
            hwindow(vII, hII, hasHalo, lane, w3);

            const bool divpath = (gi + 1 < R) || (!hasHalo && lane < 5);
            const float Nrf = (gi + 1 < R) ? (float)(gi + 1) : 20.0f;
            float A_[4], b_[4];
#pragma unroll
            for (int e = 0; e < 4; ++e) {
                float m0, m1, m2, m3, A;
                if (divpath) {
                    const int colp1 = c0 + lane * 4 + e + 1;
                    const float Ncf = (colp1 < R) ? (float)colp1 : 20.0f;
                    const float Nf = __fmul_rn(Nrf, Ncf);
                    m0 = __fdiv_rn(w0[e], Nf); m1 = __fdiv_rn(w1[e], Nf);
                    m2 = __fdiv_rn(w2[e], Nf); m3 = __fdiv_rn(w3[e], Nf);
                    const float cov = __fsub_rn(m2, __fmul_rn(m0, m1));
                    const float var = __fsub_rn(m3, __fmul_rn(m0, m0));
                    A = __fdiv_rn(cov, __fadd_rn(var, 1e-8f));   // exact at edges
                } else {
                    m0 = __fmul_rn(w0[e], inv400); m1 = __fmul_rn(w1[e], inv400);
                    m2 = __fmul_rn(w2[e], inv400); m3 = __fmul_rn(w3[e], inv400);
                    const float cov = __fsub_rn(m2, __fmul_rn(m0, m1));
                    const float var = __fsub_rn(m3, __fmul_rn(m0, m0));
                    A = __fdividef(cov, __fadd_rn(var, 1e-8f));  // fast, well-conditioned
                }
                A_[e] = A;
                b_[e] = __fsub_rn(m1, __fmul_rn(A, m0));
            }
            const int sbase = gi * (Wn / 2) + (c0 >> 1) + lane * 2;
            AB4[sbase]     = make_float4(A_[0], b_[0], A_[1], b_[1]);
            AB4[sbase + 1] = make_float4(A_[2], b_[2], A_[3], b_[3]);
        }
    }
}

__global__ void __launch_bounds__(TPB, 4)
gf_stage2(const float* __restrict__ gI, float* __restrict__ gQ)
{
    const int lane = threadIdx.x & 31;
    const int wid  = threadIdx.x >> 5;
    const int img  = blockIdx.z;
    const int c0   = (blockIdx.x * 4 + wid) * 128;
    const bool hasHalo = (c0 != 0);
    const int r0 = blockIdx.y * BANDH;
    const int r1 = r0 + BANDH;
    const int gstart = (r0 >= R - 1) ? (r0 - (R - 1)) : 0;
    const int subStart = gstart + R;

    const float4* I4  = (const float4*)(gI + (size_t)img * Hn * Wn);
    const float4* AB4 = g_AB4 + (size_t)img * Hn * (Wn / 2);
    float4* Q4 = (float4*)(gQ + (size_t)img * Hn * Wn);

    const int mi = (c0 >> 2) + lane;
    const int ai = (c0 >> 1) + lane * 2;
    const int hai = ((c0 - 20) >> 1) + lane * 2;

    float vA[4] = {0,0,0,0}, vB[4] = {0,0,0,0};
    float hA[4] = {0,0,0,0}, hB[4] = {0,0,0,0};
    const float inv400 = 1.0f / 400.0f;

    for (int gi = gstart; gi < r1; ++gi) {
        const int abase = gi * (Wn / 2);
        const float4 u0 = AB4[abase + ai];
        const float4 u1 = AB4[abase + ai + 1];
        float4 o0 = make_float4(0.f,0.f,0.f,0.f), o1 = o0;
        float4 hu0 = o0, hu1 = o0, ho0 = o0, ho1 = o0;
        const bool doSub = (gi >= subStart);
        const int obase = (gi - R) * (Wn / 2);
        if (doSub) { o0 = AB4[obase + ai]; o1 = AB4[obase + ai + 1]; }
        if (hasHalo && lane < 5) {
            hu0 = AB4[abase + hai]; hu1 = AB4[abase + hai + 1];
            if (doSub) { ho0 = AB4[obase + hai]; ho1 = AB4[obase + hai + 1]; }
        }

        {
            const float an[4] = {u0.x, u0.z, u1.x, u1.z};
            const float bn[4] = {u0.y, u0.w, u1.y, u1.w};
            const float ao[4] = {o0.x, o0.z, o1.x, o1.z};
            const float bo[4] = {o0.y, o0.w, o1.y, o1.w};
#pragma unroll
            for (int e = 0; e < 4; ++e) {
                vA[e] = __fsub_rn(__fadd_rn(vA[e], an[e]), ao[e]);
                vB[e] = __fsub_rn(__fadd_rn(vB[e], bn[e]), bo[e]);
            }
        }
        if (hasHalo) {
            const float an[4] = {hu0.x, hu0.z, hu1.x, hu1.z};
            const float bn[4] = {hu0.y, hu0.w, hu1.y, hu1.w};
            const float ao[4] = {ho0.x, ho0.z, ho1.x, ho1.z};
            const float bo[4] = {ho0.y, ho0.w, ho1.y, ho1.w};
#pragma unroll
            for (int e = 0; e < 4; ++e) {
                hA[e] = __fsub_rn(__fadd_rn(hA[e], an[e]), ao[e]);
                hB[e] = __fsub_rn(__fadd_rn(hB[e], bn[e]), bo[e]);
            }
        }

        if (gi >= r0) {
            float wA[4], wB[4];
            hwindow(vA, hA, hasHalo, lane, wA);
            hwindow(vB, hB, hasHalo, lane, wB);

            const bool divpath = (gi + 1 < R) || (!hasHalo && lane < 5);
            const float Nrf = (gi + 1 < R) ? (float)(gi + 1) : 20.0f;
            const float4 Iv = I4[(gi << 8) + mi];
            const float iv_[4] = {Iv.x, Iv.y, Iv.z, Iv.w};
            float q_[4];
#pragma unroll
            for (int e = 0; e < 4; ++e) {
                float mA, mB;
                if (divpath) {
                    const int colp1 = c0 + lane * 4 + e + 1;
                    const float Ncf = (colp1 < R) ? (float)colp1 : 20.0f;
                    const float Nf = __fmul_rn(Nrf, Ncf);
                    mA = __fdiv_rn(wA[e], Nf);
                    mB = __fdiv_rn(wB[e], Nf);
                } else {
                    mA = __fmul_rn(wA[e], inv400);
                    mB = __fmul_rn(wB[e], inv400);
                }
                q_[e] = __fadd_rn(__fmul_rn(mA, iv_[e]), mB);
            }
            Q4[(gi << 8) + mi] = make_float4(q_[0], q_[1], q_[2], q_[3]);
        }
    }
}

extern "C" void kernel_launch(void* const* d_in, const int* in_sizes, int n_in,
                              void* d_out, int out_size)
{
    (void)in_sizes; (void)n_in; (void)out_size;
    const float* I = (const float*)d_in[0];
    const float* p = (const float*)d_in[1];
    float* q = (float*)d_out;

    dim3 grid(2, NBAND, NIMG);
    gf_stage1<<<grid, TPB>>>(I, p);
    gf_stage2<<<grid, TPB>>>(I, q);
}

// round 6
// speedup vs baseline: 3.6154x; 1.2787x over previous
#include <cuda_runtime.h>

// GuidedFilter, causal box window R=20 (trailing, clamped prefix at edges), H then W.
// Stage1: box{I,p,Ip,I2} -> A,b (scratch).  Stage2: box{A,b} -> q.
//
// 1 warp = 128 columns (4/lane, float4). Vertical box: running add/subtract,
// re-reading row gi-20 from global (L2-hot), subtraction gated on band warm-up.
// Horizontal box width 20 == 5-lane reach, built from INDEPENDENT shfls.
// 20-col strip halo held redundantly by lanes 0..4 (FMA-fast always: halo only
// feeds cols >= 108 where var is well-conditioned). Main accumulators use the
// exact no-FMA sequential path only for rows < 20; exact division + sequential
// prefixes for edge columns/rows as before. No smem, no __syncthreads.

#define Hn 1024
#define Wn 1024
#define NIMG 24
#define R 20
#define NBAND 16
#define BANDH 64
#define TPB 128

__device__ float4 g_AB4[(size_t)NIMG * Hn * (Wn / 2)];

// Horizontal window of width 20 for 4 elements/lane; all shfls independent.
__device__ __forceinline__ void hwindow(const float v[4], const float hv[4],
                                        bool hasHalo, int lane, float w[4])
{
    // in-thread sequential inclusive prefixes (exactness-critical at lane 0)
    const float p0 = v[0];
    const float p1 = __fadd_rn(p0, v[1]);
    const float p2 = __fadd_rn(p1, v[2]);
    const float p3 = __fadd_rn(p2, v[3]);
    const float T  = p3;

    const float t1 = __shfl_up_sync(0xffffffffu, T, 1);
    const float t2 = __shfl_up_sync(0xffffffffu, T, 2);
    const float t3 = __shfl_up_sync(0xffffffffu, T, 3);
    const float t4 = __shfl_up_sync(0xffffffffu, T, 4);
    const float t5 = __shfl_up_sync(0xffffffffu, T, 5);
    const float s0 = __shfl_up_sync(0xffffffffu, p0, 5);
    const float s1 = __shfl_up_sync(0xffffffffu, p1, 5);
    const float s2 = __shfl_up_sync(0xffffffffu, p2, 5);
    const float s3 = t5;                    // p3 == T

    float sumT = 0.0f;
    if (lane >= 1) sumT = __fadd_rn(sumT, t1);
    if (lane >= 2) sumT = __fadd_rn(sumT, t2);
    if (lane >= 3) sumT = __fadd_rn(sumT, t3);
    if (lane >= 4) sumT = __fadd_rn(sumT, t4);
    if (lane >= 5) sumT = __fadd_rn(sumT, t5);

    // halo prefixes (lanes 0..4 hold the 20 halo cols); garbage elsewhere, unused
    const float hp0 = hv[0];
    const float hp1 = __fadd_rn(hp0, hv[1]);
    const float hp2 = __fadd_rn(hp1, hv[2]);
    const float hp3 = __fadd_rn(hp2, hv[3]);
    const float d1 = __shfl_down_sync(0xffffffffu, hp3, 1);
    const float d2 = __shfl_down_sync(0xffffffffu, hp3, 2);
    const float d3 = __shfl_down_sync(0xffffffffu, hp3, 3);
    const float d4 = __shfl_down_sync(0xffffffffu, hp3, 4);
    float hs = 0.0f;                        // suffix of halo lane-totals after this lane
    if (lane <= 3) hs = __fadd_rn(hs, d1);
    if (lane <= 2) hs = __fadd_rn(hs, d2);
    if (lane <= 1) hs = __fadd_rn(hs, d3);
    if (lane == 0) hs = __fadd_rn(hs, d4);

    const float hq0 = __fsub_rn(hp3, hp0);
    const float hq1 = __fsub_rn(hp3, hp1);
    const float hq2 = __fsub_rn(hp3, hp2);

    const float c0_ = __fadd_rn(p0, sumT);
    const float c1_ = __fadd_rn(p1, sumT);
    const float c2_ = __fadd_rn(p2, sumT);
    const float c3_ = __fadd_rn(p3, sumT);

    if (lane >= 5) {
        w[0] = __fsub_rn(c0_, s0);
        w[1] = __fsub_rn(c1_, s1);
        w[2] = __fsub_rn(c2_, s2);
        w[3] = __fsub_rn(c3_, s3);
    } else if (hasHalo) {
        w[0] = __fadd_rn(__fadd_rn(c0_, hs), hq0);
        w[1] = __fadd_rn(__fadd_rn(c1_, hs), hq1);
        w[2] = __fadd_rn(__fadd_rn(c2_, hs), hq2);
        w[3] = __fadd_rn(c3_, hs);
    } else {                                // strip 0: clamped prefix
        w[0] = c0_;
        w[1] = c1_;
        w[2] = c2_;
        w[3] = c3_;
    }
}

__global__ void __launch_bounds__(TPB, 5)
gf_stage1(const float* __restrict__ gI, const float* __restrict__ gP)
{
    const int lane = threadIdx.x & 31;
    const int wid  = threadIdx.x >> 5;
    const int img  = blockIdx.z;
    const int c0   = (blockIdx.x * 4 + wid) * 128;
    const bool hasHalo = (c0 != 0);
    const int r0 = blockIdx.y * BANDH;
    const int r1 = r0 + BANDH;
    const int gstart = (r0 >= R - 1) ? (r0 - (R - 1)) : 0;
    const int subStart = gstart + R;

    const float4* I4  = (const float4*)(gI + (size_t)img * Hn * Wn);
    const float4* P4  = (const float4*)(gP + (size_t)img * Hn * Wn);
    float4* AB4 = g_AB4 + (size_t)img * Hn * (Wn / 2);

    const int mi = (c0 >> 2) + lane;
    const int hi = ((c0 - 20) >> 2) + lane;

    float vI[4]  = {0,0,0,0}, vP[4]  = {0,0,0,0};
    float vIP[4] = {0,0,0,0}, vII[4] = {0,0,0,0};
    float hI[4]  = {0,0,0,0}, hP[4]  = {0,0,0,0};
    float hIP[4] = {0,0,0,0}, hII[4] = {0,0,0,0};
    const float inv400 = 1.0f / 400.0f;

    for (int gi = gstart; gi < r1; ++gi) {
        const int rbase = gi << 8;
        const float4 In = I4[rbase + mi];
        const float4 Pn = P4[rbase + mi];
        float4 Io = make_float4(0.f,0.f,0.f,0.f), Po = Io;
        float4 HIn = Io, HPn = Io, HIo = Io, HPo = Io;
        const bool doSub = (gi >= subStart);
        const int obase = (gi - R) << 8;
        if (doSub) { Io = I4[obase + mi]; Po = P4[obase + mi]; }
        if (hasHalo && lane < 5) {
            HIn = I4[rbase + hi]; HPn = P4[rbase + hi];
            if (doSub) { HIo = I4[obase + hi]; HPo = P4[obase + hi]; }
        }

        {
            const float in_[4] = {In.x, In.y, In.z, In.w};
            const float pn_[4] = {Pn.x, Pn.y, Pn.z, Pn.w};
            const float io_[4] = {Io.x, Io.y, Io.z, Io.w};
            const float po_[4] = {Po.x, Po.y, Po.z, Po.w};
            if (gi < R) {
                // exact sequential path (edge rows; ref-rounding bit-match)
#pragma unroll
                for (int e = 0; e < 4; ++e) {
                    vI[e]  = __fsub_rn(__fadd_rn(vI[e],  in_[e]), io_[e]);
                    vP[e]  = __fsub_rn(__fadd_rn(vP[e],  pn_[e]), po_[e]);
                    vIP[e] = __fsub_rn(__fadd_rn(vIP[e], __fmul_rn(in_[e], pn_[e])),
                                       __fmul_rn(io_[e], po_[e]));
                    vII[e] = __fsub_rn(__fadd_rn(vII[e], __fmul_rn(in_[e], in_[e])),
                                       __fmul_rn(io_[e], io_[e]));
                }
            } else {
#pragma unroll
                for (int e = 0; e < 4; ++e) {
                    vI[e]  = __fsub_rn(__fadd_rn(vI[e],  in_[e]), io_[e]);
                    vP[e]  = __fsub_rn(__fadd_rn(vP[e],  pn_[e]), po_[e]);
                    vIP[e] = fmaf(in_[e], pn_[e], fmaf(-io_[e], po_[e], vIP[e]));
                    vII[e] = fmaf(in_[e], in_[e], fmaf(-io_[e], io_[e], vII[e]));
                }
            }
        }
        if (hasHalo) {
            // halo feeds only cols >= 108 (well-conditioned): FMA always
            const float in_[4] = {HIn.x, HIn.y, HIn.z, HIn.w};
            const float pn_[4] = {HPn.x, HPn.y, HPn.z, HPn.w};
            const float io_[4] = {HIo.x, HIo.y, HIo.z, HIo.w};
            const float po_[4] = {HPo.x, HPo.y, HPo.z, HPo.w};
#pragma unroll
            for (int e = 0; e < 4; ++e) {
                hI[e]  = __fsub_rn(__fadd_rn(hI[e],  in_[e]), io_[e]);
                hP[e]  = __fsub_rn(__fadd_rn(hP[e],  pn_[e]), po_[e]);
                hIP[e] = fmaf(in_[e], pn_[e], fmaf(-io_[e], po_[e], hIP[e]));
                hII[e] = fmaf(in_[e], in_[e], fmaf(-io_[e], io_[e], hII[e]));
            }
        }

        if (gi >= r0) {
            float w0[4], w1[4], w2[4], w3[4];
            hwindow(vI,  hI,  hasHalo, lane, w0);
            hwindow(vP,  hP,  hasHalo, lane, w1);
            hwindow(vIP, hIP, hasHalo, lane, w2);
            hwindow(vII, hII, hasHalo, lane, w3);

            const bool divpath = (gi + 1 < R) || (!hasHalo && lane < 5);
            float A_[4], b_[4];
            if (divpath) {
                const float Nrf = (gi + 1 < R) ? (float)(gi + 1) : 20.0f;
#pragma unroll
                for (int e = 0; e < 4; ++e) {
                    const int colp1 = c0 + lane * 4 + e + 1;
                    const float Ncf = (colp1 < R) ? (float)colp1 : 20.0f;
                    const float Nf = __fmul_rn(Nrf, Ncf);
                    const float m0 = __fdiv_rn(w0[e], Nf);
                    const float m1 = __fdiv_rn(w1[e], Nf);
                    const float m2 = __fdiv_rn(w2[e], Nf);
                    const float m3 = __fdiv_rn(w3[e], Nf);
                    const float cov = __fsub_rn(m2, __fmul_rn(m0, m1));
                    const float var = __fsub_rn(m3, __fmul_rn(m0, m0));
                    A_[e] = __fdiv_rn(cov, __fadd_rn(var, 1e-8f));
                    b_[e] = __fsub_rn(m1, __fmul_rn(A_[e], m0));
                }
            } else {
#pragma unroll
                for (int e = 0; e < 4; ++e) {
                    const float m0 = w0[e] * inv400;
                    const float m1 = w1[e] * inv400;
                    const float m2 = w2[e] * inv400;
                    const float m3 = w3[e] * inv400;
                    const float cov = fmaf(-m0, m1, m2);
                    const float var = fmaf(-m0, m0, m3);
                    const float A = __fdividef(cov, var + 1e-8f);
                    A_[e] = A;
                    b_[e] = fmaf(-A, m0, m1);
                }
            }
            const int sbase = gi * (Wn / 2) + (c0 >> 1) + lane * 2;
            AB4[sbase]     = make_float4(A_[0], b_[0], A_[1], b_[1]);
            AB4[sbase + 1] = make_float4(A_[2], b_[2], A_[3], b_[3]);
        }
    }
}

__global__ void __launch_bounds__(TPB, 5)
gf_stage2(const float* __restrict__ gI, float* __restrict__ gQ)
{
    const int lane = threadIdx.x & 31;
    const int wid  = threadIdx.x >> 5;
    const int img  = blockIdx.z;
    const int c0   = (blockIdx.x * 4 + wid) * 128;
    const bool hasHalo = (c0 != 0);
    const int r0 = blockIdx.y * BANDH;
    const int r1 = r0 + BANDH;
    const int gstart = (r0 >= R - 1) ? (r0 - (R - 1)) : 0;
    const int subStart = gstart + R;

    const float4* I4  = (const float4*)(gI + (size_t)img * Hn * Wn);
    const float4* AB4 = g_AB4 + (size_t)img * Hn * (Wn / 2);
    float4* Q4 = (float4*)(gQ + (size_t)img * Hn * Wn);

    const int mi = (c0 >> 2) + lane;
    const int ai = (c0 >> 1) + lane * 2;
    const int hai = ((c0 - 20) >> 1) + lane * 2;

    float vA[4] = {0,0,0,0}, vB[4] = {0,0,0,0};
    float hA[4] = {0,0,0,0}, hB[4] = {0,0,0,0};
    const float inv400 = 1.0f / 400.0f;

    for (int gi = gstart; gi < r1; ++gi) {
        const int abase = gi * (Wn / 2);
        const float4 u0 = AB4[abase + ai];
        const float4 u1 = AB4[abase + ai + 1];
        float4 o0 = make_float4(0.f,0.f,0.f,0.f), o1 = o0;
        float4 hu0 = o0, hu1 = o0, ho0 = o0, ho1 = o0;
        const bool doSub = (gi >= subStart);
        const int obase = (gi - R) * (Wn / 2);
        if (doSub) { o0 = AB4[obase + ai]; o1 = AB4[obase + ai + 1]; }
        if (hasHalo && lane < 5) {
            hu0 = AB4[abase + hai]; hu1 = AB4[abase + hai + 1];
            if (doSub) { ho0 = AB4[obase + hai]; ho1 = AB4[obase + hai + 1]; }
        }

        {
            const float an[4] = {u0.x, u0.z, u1.x, u1.z};
            const float bn[4] = {u0.y, u0.w, u1.y, u1.w};
            const float ao[4] = {o0.x, o0.z, o1.x, o1.z};
            const float bo[4] = {o0.y, o0.w, o1.y, o1.w};
#pragma unroll
            for (int e = 0; e < 4; ++e) {
                vA[e] = __fsub_rn(__fadd_rn(vA[e], an[e]), ao[e]);
                vB[e] = __fsub_rn(__fadd_rn(vB[e], bn[e]), bo[e]);
            }
        }
        if (hasHalo) {
            const float an[4] = {hu0.x, hu0.z, hu1.x, hu1.z};
            const float bn[4] = {hu0.y, hu0.w, hu1.y, hu1.w};
            const float ao[4] = {ho0.x, ho0.z, ho1.x, ho1.z};
            const float bo[4] = {ho0.y, ho0.w, ho1.y, ho1.w};
#pragma unroll
            for (int e = 0; e < 4; ++e) {
                hA[e] = __fsub_rn(__fadd_rn(hA[e], an[e]), ao[e]);
                hB[e] = __fsub_rn(__fadd_rn(hB[e], bn[e]), bo[e]);
            }
        }

        if (gi >= r0) {
            float wA[4], wB[4];
            hwindow(vA, hA, hasHalo, lane, wA);
            hwindow(vB, hB, hasHalo, lane, wB);

            const bool divpath = (gi + 1 < R) || (!hasHalo && lane < 5);
            const float4 Iv = I4[(gi << 8) + mi];
            const float iv_[4] = {Iv.x, Iv.y, Iv.z, Iv.w};
            float q_[4];
            if (divpath) {
                const float Nrf = (gi + 1 < R) ? (float)(gi + 1) : 20.0f;
#pragma unroll
                for (int e = 0; e < 4; ++e) {
                    const int colp1 = c0 + lane * 4 + e + 1;
                    const float Ncf = (colp1 < R) ? (float)colp1 : 20.0f;
                    const float Nf = __fmul_rn(Nrf, Ncf);
                    const float mA = __fdiv_rn(wA[e], Nf);
                    const float mB = __fdiv_rn(wB[e], Nf);
                    q_[e] = __fadd_rn(__fmul_rn(mA, iv_[e]), mB);
                }
            } else {
#pragma unroll
                for (int e = 0; e < 4; ++e) {
                    const float mA = wA[e] * inv400;
                    const float mB = wB[e] * inv400;
                    q_[e] = fmaf(mA, iv_[e], mB);
                }
            }
            Q4[(gi << 8) + mi] = make_float4(q_[0], q_[1], q_[2], q_[3]);
        }
    }
}

extern "C" void kernel_launch(void* const* d_in, const int* in_sizes, int n_in,
                              void* d_out, int out_size)
{
    (void)in_sizes; (void)n_in; (void)out_size;
    const float* I = (const float*)d_in[0];
    const float* p = (const float*)d_in[1];
    float* q = (float*)d_out;

    dim3 grid(2, NBAND, NIMG);
    gf_stage1<<<grid, TPB>>>(I, p);
    gf_stage2<<<grid, TPB>>>(I, q);
}